// round 12
// baseline (speedup 1.0000x reference)
#include <cuda_runtime.h>

#define DIM   96
#define DIM3  (DIM * DIM * DIM)   // 884736
#define CH    24
#define CH4   (CH / 4)            // 6 float4 per voxel row
#define FEAT4 (DIM3 * CH4)        // 5308416 float4 per volume

#define B           256
#define ZERO_ILP    4
#define ZERO_N      (2 * FEAT4)                  // float4 count: out_cur + out_glb
#define ZERO_THREADS (ZERO_N / ZERO_ILP)         // 2654208 (exact)
#define ZERO_BLOCKS  (ZERO_THREADS / B)          // 10368 (exact)
#define MISC_BLOCKS  (DIM3 / 4 / B)              // 864 (4 voxels/thread)

// ---------------- scratch (device globals; no allocation allowed) ----------------
__device__ int           g_win_cur[DIM3];   // row or -1
__device__ int           g_win_glb[DIM3];   // (row<<1)|row_has_nonzero, or -1
__device__ int           g_win_tgt[DIM3];
__device__ unsigned char g_valid_vol[DIM3];
__device__ unsigned char g_occ[DIM3];

// ---------------- kernels ----------------

__global__ void k_init() {
    int i = blockIdx.x * blockDim.x + threadIdx.x;
    if (i < DIM3 / 4) {
        const int4 m1 = make_int4(-1, -1, -1, -1);
        ((int4*)g_win_cur)[i] = m1;
        ((int4*)g_win_glb)[i] = m1;
        ((int4*)g_win_tgt)[i] = m1;
        ((int*)g_valid_vol)[i] = 0;
        ((int*)g_occ)[i] = 0;
    }
}

// Pure streaming zero of out_cur + out_glb (contiguous 170MB). No loads,
// no dependencies -> launches at t=0 and hides the whole scatter chain.
__global__ void k_zero(float4* __restrict__ base) {
    int i = blockIdx.x * B + threadIdx.x;
    const float4 z = make_float4(0.f, 0.f, 0.f, 0.f);
    #pragma unroll
    for (int k = 0; k < ZERO_ILP; ++k)
        __stcs(&base[i + k * ZERO_THREADS], z);
}

// Fused: current-fragment scatter (range [0, n_cur)) and target scatters.
// atomicMax(row-priority) reproduces XLA's sequential last-write-wins.
__global__ void k_scatter_a(const int* __restrict__ cc,
                            const int* __restrict__ gm,
                            const int* __restrict__ occ,
                            const int* __restrict__ gct,
                            const int* __restrict__ ct,
                            const int* __restrict__ origin,
                            float* __restrict__ out_vt,
                            int n_cur, int n_g, int n_c) {
    int i = blockIdx.x * blockDim.x + threadIdx.x;
    if (i < n_cur) {
        int x = cc[3 * i], y = cc[3 * i + 1], z = cc[3 * i + 2];
        int v = (x * DIM + y) * DIM + z;
        atomicMax(&g_win_cur[v], i);
        if (gm[i] != 0)  g_valid_vol[v] = 1;
        if (occ[i] != 0) g_occ[v] = 1;
        return;
    }
    int j = i - n_cur;
    if (j < n_g) {
        // global target rows scattered first -> lower priority band [0, n_g)
        int x = gct[3 * j]     - origin[0];
        int y = gct[3 * j + 1] - origin[1];
        int z = gct[3 * j + 2] - origin[2];
        bool inb = ((unsigned)x < DIM) && ((unsigned)y < DIM) && ((unsigned)z < DIM);
        out_vt[j] = inb ? 1.0f : 0.0f;
        if (inb) atomicMax(&g_win_tgt[(x * DIM + y) * DIM + z], j);
    } else if (j < n_g + n_c) {
        // current-fragment target rows scattered second -> win ties
        int t = j - n_g;
        int x = ct[3 * t], y = ct[3 * t + 1], z = ct[3 * t + 2];
        atomicMax(&g_win_tgt[(x * DIM + y) * DIM + z], n_g + t);
    }
}

// Global rows: bounds test, visibility gather, emit valid/near_mask,
// record packed winner (row<<1 | row_any_nonzero).
__global__ void k_scatter_glb(const int* __restrict__ gc,
                              const float4* __restrict__ glb_vals,
                              const int* __restrict__ origin,
                              float* __restrict__ out_valid,
                              float* __restrict__ out_near,
                              int n) {
    int i = blockIdx.x * blockDim.x + threadIdx.x;
    if (i >= n) return;
    int x = gc[3 * i]     - origin[0];
    int y = gc[3 * i + 1] - origin[1];
    int z = gc[3 * i + 2] - origin[2];
    bool inb = ((unsigned)x < DIM) && ((unsigned)y < DIM) && ((unsigned)z < DIM);
    bool valid = false;
    if (inb) {
        int v = (x * DIM + y) * DIM + z;
        valid = (g_valid_vol[v] != 0);
        if (valid) {
            bool nz = false;
            #pragma unroll
            for (int q = 0; q < CH4; ++q) {
                float4 r = glb_vals[i * CH4 + q];
                nz |= (r.x != 0.0f) | (r.y != 0.0f) | (r.z != 0.0f) | (r.w != 0.0f);
            }
            atomicMax(&g_win_glb[v], (i << 1) | (nz ? 1 : 0));
        }
    }
    out_valid[i] = valid ? 1.0f : 0.0f;
    out_near[i]  = (inb && !valid) ? 1.0f : 0.0f;
}

// Dense target_volume + updated_mask (7MB total) — runs on s1, hidden
// under k_zero. 4 voxels/thread, int4 winner loads, float4 stcs stores.
__global__ void k_misc(const float* __restrict__ tsdf_tgt,
                       const float* __restrict__ gtsdf_tgt,
                       float4* __restrict__ out_tgt,
                       float4* __restrict__ out_mask,
                       int n_gtgt) {
    int t4 = blockIdx.x * B + threadIdx.x;
    int4 wt = ((const int4*)g_win_tgt)[t4];
    int4 wg = ((const int4*)g_win_glb)[t4];
    unsigned int occ4 = ((const unsigned int*)g_occ)[t4];

    float tv[4];
    int wts[4] = {wt.x, wt.y, wt.z, wt.w};
    #pragma unroll
    for (int k = 0; k < 4; ++k) {
        int w = wts[k];
        if (w < 0)            tv[k] = 1.0f;
        else if (w >= n_gtgt) tv[k] = tsdf_tgt[w - n_gtgt];
        else                  tv[k] = gtsdf_tgt[w];
    }
    __stcs(&out_tgt[t4], make_float4(tv[0], tv[1], tv[2], tv[3]));

    int wgs[4] = {wg.x, wg.y, wg.z, wg.w};
    float mv[4];
    #pragma unroll
    for (int k = 0; k < 4; ++k) {
        bool m = ((occ4 >> (8 * k)) & 0xFF) != 0;
        m |= (wgs[k] >= 0) && (wgs[k] & 1);
        mv[k] = m ? 1.0f : 0.0f;
    }
    __stcs(&out_mask[t4], make_float4(mv[0], mv[1], mv[2], mv[3]));
}

// Sparse winner writes: 6 threads per candidate row (one float4 chunk each).
// Range [0, n_cur): current rows -> out_cur if win_cur[v]==row.
// Range [n_cur, n_cur+n_glb): global rows -> out_glb if win_glb[v]>>1==row.
// Exactly one winner per voxel writes; everything else was pre-zeroed.
__global__ void k_sparse(const int* __restrict__ cc,
                         const float4* __restrict__ cur_vals,
                         const int* __restrict__ gc,
                         const float4* __restrict__ glb_vals,
                         const int* __restrict__ origin,
                         float4* __restrict__ out_cur,
                         float4* __restrict__ out_glb,
                         int n_cur, int n_glb) {
    int k = blockIdx.x * B + threadIdx.x;
    int r = k / CH4;
    int q = k - r * CH4;
    if (r < n_cur) {
        int x = cc[3 * r], y = cc[3 * r + 1], z = cc[3 * r + 2];
        int v = (x * DIM + y) * DIM + z;
        if (g_win_cur[v] == r)
            __stcs(&out_cur[v * CH4 + q], cur_vals[r * CH4 + q]);
        return;
    }
    int g = r - n_cur;
    if (g >= n_glb) return;
    int x = gc[3 * g]     - origin[0];
    int y = gc[3 * g + 1] - origin[1];
    int z = gc[3 * g + 2] - origin[2];
    if (((unsigned)x < DIM) && ((unsigned)y < DIM) && ((unsigned)z < DIM)) {
        int v = (x * DIM + y) * DIM + z;
        int w = g_win_glb[v];
        if ((w >> 1) == g && w >= 0)
            __stcs(&out_glb[v * CH4 + q], glb_vals[g * CH4 + q]);
    }
}

// ---------------- launch ----------------

extern "C" void kernel_launch(void* const* d_in, const int* in_sizes, int n_in,
                              void* d_out, int out_size) {
    const int*   cur_coords = (const int*)d_in[0];
    const float* cur_vals   = (const float*)d_in[1];
    const int*   glb_coords = (const int*)d_in[2];
    const float* glb_vals   = (const float*)d_in[3];
    const int*   ct_coords  = (const int*)d_in[4];
    const float* tsdf_tgt   = (const float*)d_in[5];
    const int*   gct_coords = (const int*)d_in[6];
    const float* gtsdf_tgt  = (const float*)d_in[7];
    const int*   origin     = (const int*)d_in[8];
    const int*   grid_mask  = (const int*)d_in[9];   // bool promoted to 4-byte
    const int*   occupancy  = (const int*)d_in[10];  // bool promoted to 4-byte

    const int n_cur  = in_sizes[0] / 3;
    const int n_glb  = in_sizes[2] / 3;
    const int n_tgt  = in_sizes[4] / 3;
    const int n_gtgt = in_sizes[6] / 3;

    float* out = (float*)d_out;
    // output layout: tuple order, flattened, float32
    float* out_mask  = out;                          // DIM3
    float* out_cur   = out_mask + DIM3;              // DIM3*CH
    float* out_glb   = out_cur + (size_t)DIM3 * CH;  // DIM3*CH
    float* out_tgt   = out_glb + (size_t)DIM3 * CH;  // DIM3
    float* out_valid = out_tgt + DIM3;               // n_glb
    float* out_vt    = out_valid + n_glb;            // n_gtgt
    float* out_near  = out_vt + n_gtgt;              // n_glb

    // Forked-stream capture (event fork/join). Stream/events created per call
    // and deliberately not destroyed (destroying mid-capture invalidates the
    // graph; kernel_launch is called only for correctness + capture, so the
    // leak is bounded and involves no device memory).
    cudaStream_t s1;
    cudaStreamCreateWithFlags(&s1, cudaStreamNonBlocking);
    cudaEvent_t e_fork, e_chain;
    cudaEventCreateWithFlags(&e_fork,  cudaEventDisableTiming);
    cudaEventCreateWithFlags(&e_chain, cudaEventDisableTiming);

    cudaEventRecord(e_fork, 0);
    cudaStreamWaitEvent(s1, e_fork, 0);

    // main stream: the big dependency-free zero of out_cur + out_glb
    k_zero<<<ZERO_BLOCKS, B>>>((float4*)out_cur);

    // s1: scatter chain + small dense outputs, hidden under k_zero
    const int initg = (DIM3 / 4 + B - 1) / B;
    k_init<<<initg, B, 0, s1>>>();
    int n_a = n_cur + n_gtgt + n_tgt;
    k_scatter_a<<<(n_a + B - 1) / B, B, 0, s1>>>(cur_coords, grid_mask, occupancy,
                                                 gct_coords, ct_coords, origin,
                                                 out_vt, n_cur, n_gtgt, n_tgt);
    k_scatter_glb<<<(n_glb + B - 1) / B, B, 0, s1>>>(glb_coords, (const float4*)glb_vals,
                                                     origin, out_valid, out_near, n_glb);
    k_misc<<<MISC_BLOCKS, B, 0, s1>>>(tsdf_tgt, gtsdf_tgt,
                                      (float4*)out_tgt, (float4*)out_mask, n_gtgt);
    cudaEventRecord(e_chain, s1);

    // join, then sparse winner writes into the zeroed volumes
    cudaStreamWaitEvent(0, e_chain, 0);
    int n_rows = (n_cur + n_glb) * CH4;
    k_sparse<<<(n_rows + B - 1) / B, B>>>(cur_coords, (const float4*)cur_vals,
                                          glb_coords, (const float4*)glb_vals,
                                          origin,
                                          (float4*)out_cur, (float4*)out_glb,
                                          n_cur, n_glb);
}

// round 14
// speedup vs baseline: 1.0572x; 1.0572x over previous
#include <cuda_runtime.h>

#define DIM   96
#define DIM3  (DIM * DIM * DIM)   // 884736
#define CH    24
#define CH4   (CH / 4)            // 6 float4 per voxel row
#define FEAT4 (DIM3 * CH4)        // 5308416 float4 per volume

#define B         256
#define FILL_ILP  4
#define FILL_THREADS (FEAT4 / FILL_ILP)          // 1327104 (exact)
#define FILL_BLOCKS  (FILL_THREADS / B)          // 5184 (exact)
#define MISC_BLOCKS  (DIM3 / 4 / B)              // 864 (4 voxels/thread)

// ---------------- scratch (device globals; no allocation allowed) ----------------
// Packed winner pair: .x = win_cur (row or -1), .y = win_glb ((row<<1)|nz or -1)
__device__ int2          g_win_cg[DIM3];
__device__ int           g_win_tgt[DIM3];
__device__ unsigned char g_valid_vol[DIM3];
__device__ unsigned char g_occ[DIM3];

// ---------------- kernels ----------------

// main-stream init: just valid_vol (feeds scat_valid -> scatter_glb chain)
__global__ void k_init_v() {
    int i = blockIdx.x * blockDim.x + threadIdx.x;
    if (i < DIM3 / 4)
        ((int*)g_valid_vol)[i] = 0;
}

// s1 init: winner arrays + occ (feeds scatter_rest; scatter_glb waits on event)
__global__ void k_init_b() {
    int i = blockIdx.x * blockDim.x + threadIdx.x;
    const int4 m1 = make_int4(-1, -1, -1, -1);
    if (i < DIM3 / 2)
        ((int4*)g_win_cg)[i] = m1;          // 2 voxels per int4
    if (i < DIM3 / 4) {
        ((int4*)g_win_tgt)[i] = m1;
        ((int*)g_occ)[i] = 0;
    }
}

// valid_volume only: cc + grid_mask. Benign same-value write races.
__global__ void k_scat_valid(const int* __restrict__ cc,
                             const int* __restrict__ gm,
                             int n) {
    int i = blockIdx.x * blockDim.x + threadIdx.x;
    if (i >= n) return;
    if (gm[i] != 0) {
        int x = cc[3 * i], y = cc[3 * i + 1], z = cc[3 * i + 2];
        g_valid_vol[(x * DIM + y) * DIM + z] = 1;
    }
}

// Everything else from the old scatter_a: win_cur, occ, target winners, out_vt.
// Runs on s1, concurrent with scatter_glb (disjoint scratch words).
// atomicMax(row-priority) reproduces XLA's sequential last-write-wins.
__global__ void k_scatter_rest(const int* __restrict__ cc,
                               const int* __restrict__ occ,
                               const int* __restrict__ gct,
                               const int* __restrict__ ct,
                               const int* __restrict__ origin,
                               float* __restrict__ out_vt,
                               int n_cur, int n_g, int n_c) {
    int i = blockIdx.x * blockDim.x + threadIdx.x;
    if (i < n_cur) {
        int x = cc[3 * i], y = cc[3 * i + 1], z = cc[3 * i + 2];
        int v = (x * DIM + y) * DIM + z;
        atomicMax(&g_win_cg[v].x, i);
        if (occ[i] != 0) g_occ[v] = 1;
        return;
    }
    int j = i - n_cur;
    if (j < n_g) {
        // global target rows scattered first -> lower priority band [0, n_g)
        int x = gct[3 * j]     - origin[0];
        int y = gct[3 * j + 1] - origin[1];
        int z = gct[3 * j + 2] - origin[2];
        bool inb = ((unsigned)x < DIM) && ((unsigned)y < DIM) && ((unsigned)z < DIM);
        out_vt[j] = inb ? 1.0f : 0.0f;
        if (inb) atomicMax(&g_win_tgt[(x * DIM + y) * DIM + z], j);
    } else if (j < n_g + n_c) {
        // current-fragment target rows scattered second -> win ties
        int t = j - n_g;
        int x = ct[3 * t], y = ct[3 * t + 1], z = ct[3 * t + 2];
        atomicMax(&g_win_tgt[(x * DIM + y) * DIM + z], n_g + t);
    }
}

// Global rows: bounds test, visibility gather, emit valid/near_mask,
// record packed winner (row<<1 | row_any_nonzero) into g_win_cg[v].y.
__global__ void k_scatter_glb(const int* __restrict__ gc,
                              const float4* __restrict__ glb_vals,
                              const int* __restrict__ origin,
                              float* __restrict__ out_valid,
                              float* __restrict__ out_near,
                              int n) {
    int i = blockIdx.x * blockDim.x + threadIdx.x;
    if (i >= n) return;
    int x = gc[3 * i]     - origin[0];
    int y = gc[3 * i + 1] - origin[1];
    int z = gc[3 * i + 2] - origin[2];
    bool inb = ((unsigned)x < DIM) && ((unsigned)y < DIM) && ((unsigned)z < DIM);
    bool valid = false;
    if (inb) {
        int v = (x * DIM + y) * DIM + z;
        valid = (g_valid_vol[v] != 0);
        if (valid) {
            bool nz = false;
            #pragma unroll
            for (int q = 0; q < CH4; ++q) {
                float4 r = glb_vals[i * CH4 + q];
                nz |= (r.x != 0.0f) | (r.y != 0.0f) | (r.z != 0.0f) | (r.w != 0.0f);
            }
            atomicMax(&g_win_cg[v].y, (i << 1) | (nz ? 1 : 0));
        }
    }
    out_valid[i] = valid ? 1.0f : 0.0f;
    out_near[i]  = (inb && !valid) ? 1.0f : 0.0f;
}

// Fused dense fill (byte-identical to R8's best). Misc blocks first,
// 4 voxels/thread vectorized; fill blocks 4-way ILP over grid-strided
// float4 slices; one LDG.64 per element fetches both winners; __stcs
// streaming stores keep tables/winners L2-resident.
__global__ void k_fill(const float4* __restrict__ cur_vals,
                       const float4* __restrict__ glb_vals,
                       const float* __restrict__ tsdf_tgt,
                       const float* __restrict__ gtsdf_tgt,
                       float4* __restrict__ out_cur,
                       float4* __restrict__ out_glb,
                       float4* __restrict__ out_tgt,
                       float4* __restrict__ out_mask,
                       int n_gtgt) {
    int b = blockIdx.x;
    if (b >= MISC_BLOCKS) {
        int base = (b - MISC_BLOCKS) * B + threadIdx.x;
        const float4 zero = make_float4(0.f, 0.f, 0.f, 0.f);
        int e[FILL_ILP];
        int2 w[FILL_ILP];
        #pragma unroll
        for (int k = 0; k < FILL_ILP; ++k) {
            e[k] = base + k * FILL_THREADS;
            w[k] = g_win_cg[e[k] / CH4];
        }
        #pragma unroll
        for (int k = 0; k < FILL_ILP; ++k) {
            int v = e[k] / CH4;
            int q = e[k] - v * CH4;
            float4 rc = (w[k].x >= 0) ? cur_vals[w[k].x * CH4 + q] : zero;
            float4 rg = (w[k].y >= 0) ? glb_vals[(w[k].y >> 1) * CH4 + q] : zero;
            __stcs(&out_cur[e[k]], rc);
            __stcs(&out_glb[e[k]], rg);
        }
        return;
    }
    // misc: 4 voxels per thread; int4 loads cover 2 packed winner pairs each
    int t4 = b * B + threadIdx.x;
    int4 wt = ((const int4*)g_win_tgt)[t4];
    int4 wp0 = ((const int4*)g_win_cg)[t4 * 2 + 0];   // voxels v0,v0+1
    int4 wp1 = ((const int4*)g_win_cg)[t4 * 2 + 1];   // voxels v0+2,v0+3
    unsigned int occ4 = ((const unsigned int*)g_occ)[t4];

    float tv[4];
    int wts[4] = {wt.x, wt.y, wt.z, wt.w};
    #pragma unroll
    for (int k = 0; k < 4; ++k) {
        int w = wts[k];
        if (w < 0)            tv[k] = 1.0f;
        else if (w >= n_gtgt) tv[k] = tsdf_tgt[w - n_gtgt];
        else                  tv[k] = gtsdf_tgt[w];
    }
    __stcs(&out_tgt[t4], make_float4(tv[0], tv[1], tv[2], tv[3]));

    int wgs[4] = {wp0.y, wp0.w, wp1.y, wp1.w};
    float mv[4];
    #pragma unroll
    for (int k = 0; k < 4; ++k) {
        bool m = ((occ4 >> (8 * k)) & 0xFF) != 0;
        m |= (wgs[k] >= 0) && (wgs[k] & 1);
        mv[k] = m ? 1.0f : 0.0f;
    }
    __stcs(&out_mask[t4], make_float4(mv[0], mv[1], mv[2], mv[3]));
}

// ---------------- launch ----------------

extern "C" void kernel_launch(void* const* d_in, const int* in_sizes, int n_in,
                              void* d_out, int out_size) {
    const int*   cur_coords = (const int*)d_in[0];
    const float* cur_vals   = (const float*)d_in[1];
    const int*   glb_coords = (const int*)d_in[2];
    const float* glb_vals   = (const float*)d_in[3];
    const int*   ct_coords  = (const int*)d_in[4];
    const float* tsdf_tgt   = (const float*)d_in[5];
    const int*   gct_coords = (const int*)d_in[6];
    const float* gtsdf_tgt  = (const float*)d_in[7];
    const int*   origin     = (const int*)d_in[8];
    const int*   grid_mask  = (const int*)d_in[9];   // bool promoted to 4-byte
    const int*   occupancy  = (const int*)d_in[10];  // bool promoted to 4-byte

    const int n_cur  = in_sizes[0] / 3;
    const int n_glb  = in_sizes[2] / 3;
    const int n_tgt  = in_sizes[4] / 3;
    const int n_gtgt = in_sizes[6] / 3;

    float* out = (float*)d_out;
    // output layout: tuple order, flattened, float32
    float* out_mask  = out;                          // DIM3
    float* out_cur   = out_mask + DIM3;              // DIM3*CH
    float* out_glb   = out_cur + (size_t)DIM3 * CH;  // DIM3*CH
    float* out_tgt   = out_glb + (size_t)DIM3 * CH;  // DIM3
    float* out_valid = out_tgt + DIM3;               // n_glb
    float* out_vt    = out_valid + n_glb;            // n_gtgt
    float* out_near  = out_vt + n_gtgt;              // n_glb

    // Forked-stream capture (event fork/join). Stream/events created per call
    // and deliberately not destroyed (destroying mid-capture invalidates the
    // graph; bounded leak, no device memory involved).
    cudaStream_t s1;
    cudaStreamCreateWithFlags(&s1, cudaStreamNonBlocking);
    cudaEvent_t e_fork, e_ib, e_rest;
    cudaEventCreateWithFlags(&e_fork, cudaEventDisableTiming);
    cudaEventCreateWithFlags(&e_ib,   cudaEventDisableTiming);
    cudaEventCreateWithFlags(&e_rest, cudaEventDisableTiming);

    cudaEventRecord(e_fork, 0);
    cudaStreamWaitEvent(s1, e_fork, 0);

    const int initg_v = (DIM3 / 4 + B - 1) / B;
    const int initg_b = (DIM3 / 2 + B - 1) / B;

    // s1 branch: winner/occ init, then win_cur + occ + target scatters
    k_init_b<<<initg_b, B, 0, s1>>>();
    cudaEventRecord(e_ib, s1);
    int n_a = n_cur + n_gtgt + n_tgt;
    k_scatter_rest<<<(n_a + B - 1) / B, B, 0, s1>>>(cur_coords, occupancy,
                                                    gct_coords, ct_coords, origin,
                                                    out_vt, n_cur, n_gtgt, n_tgt);
    cudaEventRecord(e_rest, s1);

    // main branch: valid_vol init + build, then scatter_glb (overlaps scatter_rest)
    k_init_v<<<initg_v, B>>>();
    k_scat_valid<<<(n_cur + B - 1) / B, B>>>(cur_coords, grid_mask, n_cur);
    cudaStreamWaitEvent(0, e_ib, 0);       // win_cg must be initialized
    k_scatter_glb<<<(n_glb + B - 1) / B, B>>>(glb_coords, (const float4*)glb_vals,
                                              origin, out_valid, out_near, n_glb);

    // join with s1, then the untouched fused fill
    cudaStreamWaitEvent(0, e_rest, 0);
    k_fill<<<MISC_BLOCKS + FILL_BLOCKS, B>>>((const float4*)cur_vals, (const float4*)glb_vals,
                                             tsdf_tgt, gtsdf_tgt,
                                             (float4*)out_cur, (float4*)out_glb,
                                             (float4*)out_tgt, (float4*)out_mask, n_gtgt);
}

// round 15
// speedup vs baseline: 1.1688x; 1.1056x over previous
#include <cuda_runtime.h>

#define DIM   96
#define DIM3  (DIM * DIM * DIM)   // 884736
#define CH    24
#define CH4   (CH / 4)            // 6 float4 per voxel row
#define FEAT4 (DIM3 * CH4)        // 5308416 float4 elements per volume

#define B         256
#define FILL_ILP  6
#define FILL_THREADS (FEAT4 / FILL_ILP)          // 884736 (exact)
#define FILL_BLOCKS  (FILL_THREADS / B)          // 3456 (exact)
#define MISC_BLOCKS  (DIM3 / 4 / B)              // 864 (exact, 4 voxels/thread)

// ---------------- scratch (device globals; no allocation allowed) ----------------
// Packed winner pair: .x = win_cur (row or -1), .y = win_glb ((row<<1)|nz or -1)
__device__ int2          g_win_cg[DIM3];
__device__ int           g_win_tgt[DIM3];
__device__ unsigned char g_valid_vol[DIM3];
__device__ unsigned char g_occ[DIM3];

// ---------------- kernels ----------------

// Vectorized scratch reset: winners = -1 (int4), flags = 0.
__global__ void k_init() {
    int i = blockIdx.x * blockDim.x + threadIdx.x;
    const int4 m1 = make_int4(-1, -1, -1, -1);
    if (i < DIM3 / 2)
        ((int4*)g_win_cg)[i] = m1;          // 2 voxels per int4
    if (i < DIM3 / 4) {
        ((int4*)g_win_tgt)[i] = m1;
        ((int*)g_valid_vol)[i] = 0;
        ((int*)g_occ)[i] = 0;
    }
}

// Fused: current-fragment scatter (range [0, n_cur)) and target scatters
// (range [n_cur, n_cur + n_gtgt + n_tgt)). Independent work, one launch.
// atomicMax(row-priority) reproduces XLA's sequential last-write-wins.
__global__ void k_scatter_a(const int* __restrict__ cc,
                            const int* __restrict__ gm,
                            const int* __restrict__ occ,
                            const int* __restrict__ gct,
                            const int* __restrict__ ct,
                            const int* __restrict__ origin,
                            float* __restrict__ out_vt,
                            int n_cur, int n_g, int n_c) {
    int i = blockIdx.x * blockDim.x + threadIdx.x;
    if (i < n_cur) {
        int x = cc[3 * i], y = cc[3 * i + 1], z = cc[3 * i + 2];
        int v = (x * DIM + y) * DIM + z;
        atomicMax(&g_win_cg[v].x, i);
        if (gm[i] != 0)  g_valid_vol[v] = 1;
        if (occ[i] != 0) g_occ[v] = 1;
        return;
    }
    int j = i - n_cur;
    if (j < n_g) {
        // global target rows: scattered first -> lower priority band [0, n_g)
        int x = gct[3 * j]     - origin[0];
        int y = gct[3 * j + 1] - origin[1];
        int z = gct[3 * j + 2] - origin[2];
        bool inb = ((unsigned)x < DIM) && ((unsigned)y < DIM) && ((unsigned)z < DIM);
        out_vt[j] = inb ? 1.0f : 0.0f;
        if (inb) atomicMax(&g_win_tgt[(x * DIM + y) * DIM + z], j);
    } else if (j < n_g + n_c) {
        // current-fragment target rows: scattered second -> win ties
        int t = j - n_g;
        int x = ct[3 * t], y = ct[3 * t + 1], z = ct[3 * t + 2];
        atomicMax(&g_win_tgt[(x * DIM + y) * DIM + z], n_g + t);
    }
}

// Global rows: shift by origin, in-bounds test, gather valid_volume,
// emit `valid`/`near_mask`, record packed winner (row<<1 | row_any_nonzero).
__global__ void k_scatter_glb(const int* __restrict__ gc,
                              const float4* __restrict__ glb_vals,
                              const int* __restrict__ origin,
                              float* __restrict__ out_valid,
                              float* __restrict__ out_near,
                              int n) {
    int i = blockIdx.x * blockDim.x + threadIdx.x;
    if (i >= n) return;
    int x = gc[3 * i]     - origin[0];
    int y = gc[3 * i + 1] - origin[1];
    int z = gc[3 * i + 2] - origin[2];
    bool inb = ((unsigned)x < DIM) && ((unsigned)y < DIM) && ((unsigned)z < DIM);
    bool valid = false;
    if (inb) {
        int v = (x * DIM + y) * DIM + z;
        valid = (g_valid_vol[v] != 0);
        if (valid) {
            bool nz = false;
            #pragma unroll
            for (int q = 0; q < CH4; ++q) {
                float4 r = glb_vals[i * CH4 + q];
                nz |= (r.x != 0.0f) | (r.y != 0.0f) | (r.z != 0.0f) | (r.w != 0.0f);
            }
            atomicMax(&g_win_cg[v].y, (i << 1) | (nz ? 1 : 0));
        }
    }
    out_valid[i] = valid ? 1.0f : 0.0f;
    out_near[i]  = (inb && !valid) ? 1.0f : 0.0f;
}

// Fused dense fill. Misc blocks come FIRST (no ragged tail behind heavy fill
// blocks) and are vectorized 4 voxels/thread. Fill blocks: 6-way ILP over
// grid-strided float4 slices; one LDG.64 fetches both winners per element;
// __stcs streaming stores keep tables/winners L2-resident (output write-once).
__global__ void k_fill(const float4* __restrict__ cur_vals,
                       const float4* __restrict__ glb_vals,
                       const float* __restrict__ tsdf_tgt,
                       const float* __restrict__ gtsdf_tgt,
                       float4* __restrict__ out_cur,
                       float4* __restrict__ out_glb,
                       float4* __restrict__ out_tgt,
                       float4* __restrict__ out_mask,
                       int n_gtgt) {
    int b = blockIdx.x;
    if (b >= MISC_BLOCKS) {
        int base = (b - MISC_BLOCKS) * B + threadIdx.x;
        const float4 zero = make_float4(0.f, 0.f, 0.f, 0.f);
        int e[FILL_ILP];
        int2 w[FILL_ILP];
        #pragma unroll
        for (int k = 0; k < FILL_ILP; ++k) {
            e[k] = base + k * FILL_THREADS;
            w[k] = g_win_cg[e[k] / CH4];
        }
        #pragma unroll
        for (int k = 0; k < FILL_ILP; ++k) {
            int v = e[k] / CH4;
            int q = e[k] - v * CH4;
            float4 rc = (w[k].x >= 0) ? cur_vals[w[k].x * CH4 + q] : zero;
            float4 rg = (w[k].y >= 0) ? glb_vals[(w[k].y >> 1) * CH4 + q] : zero;
            __stcs(&out_cur[e[k]], rc);
            __stcs(&out_glb[e[k]], rg);
        }
        return;
    }
    // misc: 4 voxels per thread; int4 loads cover 2 packed winner pairs each
    int t4 = b * B + threadIdx.x;            // float4 index into out_tgt/out_mask
    int4 wt = ((const int4*)g_win_tgt)[t4];
    int4 wp0 = ((const int4*)g_win_cg)[t4 * 2 + 0];   // voxels v0,v0+1: (cur,glb,cur,glb)
    int4 wp1 = ((const int4*)g_win_cg)[t4 * 2 + 1];   // voxels v0+2,v0+3
    unsigned int occ4 = ((const unsigned int*)g_occ)[t4];

    float tv[4];
    int wts[4] = {wt.x, wt.y, wt.z, wt.w};
    #pragma unroll
    for (int k = 0; k < 4; ++k) {
        int w = wts[k];
        if (w < 0)            tv[k] = 1.0f;
        else if (w >= n_gtgt) tv[k] = tsdf_tgt[w - n_gtgt];
        else                  tv[k] = gtsdf_tgt[w];
    }
    __stcs(&out_tgt[t4], make_float4(tv[0], tv[1], tv[2], tv[3]));

    int wgs[4] = {wp0.y, wp0.w, wp1.y, wp1.w};
    float mv[4];
    #pragma unroll
    for (int k = 0; k < 4; ++k) {
        bool m = ((occ4 >> (8 * k)) & 0xFF) != 0;
        m |= (wgs[k] >= 0) && (wgs[k] & 1);
        mv[k] = m ? 1.0f : 0.0f;
    }
    __stcs(&out_mask[t4], make_float4(mv[0], mv[1], mv[2], mv[3]));
}

// ---------------- launch ----------------

extern "C" void kernel_launch(void* const* d_in, const int* in_sizes, int n_in,
                              void* d_out, int out_size) {
    const int*   cur_coords = (const int*)d_in[0];
    const float* cur_vals   = (const float*)d_in[1];
    const int*   glb_coords = (const int*)d_in[2];
    const float* glb_vals   = (const float*)d_in[3];
    const int*   ct_coords  = (const int*)d_in[4];
    const float* tsdf_tgt   = (const float*)d_in[5];
    const int*   gct_coords = (const int*)d_in[6];
    const float* gtsdf_tgt  = (const float*)d_in[7];
    const int*   origin     = (const int*)d_in[8];
    const int*   grid_mask  = (const int*)d_in[9];   // bool promoted to 4-byte
    const int*   occupancy  = (const int*)d_in[10];  // bool promoted to 4-byte

    const int n_cur  = in_sizes[0] / 3;
    const int n_glb  = in_sizes[2] / 3;
    const int n_tgt  = in_sizes[4] / 3;
    const int n_gtgt = in_sizes[6] / 3;

    float* out = (float*)d_out;
    // output layout: tuple order, flattened, float32
    float* out_mask  = out;                          // DIM3
    float* out_cur   = out_mask + DIM3;              // DIM3*CH
    float* out_glb   = out_cur + (size_t)DIM3 * CH;  // DIM3*CH
    float* out_tgt   = out_glb + (size_t)DIM3 * CH;  // DIM3
    float* out_valid = out_tgt + DIM3;               // n_glb
    float* out_vt    = out_valid + n_glb;            // n_gtgt
    float* out_near  = out_vt + n_gtgt;              // n_glb

    k_init<<<(DIM3 / 2 + B - 1) / B, B>>>();

    int n_a = n_cur + n_gtgt + n_tgt;
    k_scatter_a<<<(n_a + B - 1) / B, B>>>(cur_coords, grid_mask, occupancy,
                                          gct_coords, ct_coords, origin,
                                          out_vt, n_cur, n_gtgt, n_tgt);

    k_scatter_glb<<<(n_glb + B - 1) / B, B>>>(glb_coords, (const float4*)glb_vals,
                                              origin, out_valid, out_near, n_glb);

    k_fill<<<MISC_BLOCKS + FILL_BLOCKS, B>>>((const float4*)cur_vals, (const float4*)glb_vals,
                                             tsdf_tgt, gtsdf_tgt,
                                             (float4*)out_cur, (float4*)out_glb,
                                             (float4*)out_tgt, (float4*)out_mask, n_gtgt);
}